// round 6
// baseline (speedup 1.0000x reference)
#include <cuda_runtime.h>
#include <cuda_bf16.h>

// BiLSTM: B=128, S=1024, D=128, H=256, fp32.
// Phase 1: zx[dir][col][t*128+b] = bias[col] + sum_{k<128} W[g,h,k]*x[k*131072+t*128+b]
// Phase 2: persistent recurrence. CTA = (dir, 8 units, 64-batch half).
//   Lane = (unit u=lane&7, 4 batches). Warps 0-3 = team0 (k<128), 4-7 = team1 (k>=128);
//   per-step cross-team reduction in smem. Weights pre-duplicated (w,w) in smem so
//   batch-pair packed fma.rn.f32x2 needs zero mov instructions.

#define S_LEN 1024
#define NTB   131072
#define ZX_DIR ((size_t)1024 * (size_t)NTB)

typedef unsigned long long ull;

__device__ float g_zx[2ull * 1024ull * NTB];   // 1 GB scratch
__device__ float g_h[2][2][256 * 128];         // [dir][buf][u][b]
__device__ int   g_flags[2][64];

__device__ __forceinline__ ull dup2(float x) {
    ull r; asm("mov.b64 %0, {%1, %1};" : "=l"(r) : "f"(x)); return r;
}
__device__ __forceinline__ void unpack2(ull v, float& lo, float& hi) {
    asm("mov.b64 {%0, %1}, %2;" : "=f"(lo), "=f"(hi) : "l"(v));
}
__device__ __forceinline__ void fma2(ull& acc, ull a, ull b) {
    asm("fma.rn.f32x2 %0, %1, %2, %0;" : "+l"(acc) : "l"(a), "l"(b));
}
__device__ __forceinline__ void cp_async16(void* dst, const void* src) {
    unsigned d = (unsigned)__cvta_generic_to_shared(dst);
    asm volatile("cp.async.cg.shared.global [%0], [%1], 16;" :: "r"(d), "l"(src) : "memory");
}
__device__ __forceinline__ void cp_commit() {
    asm volatile("cp.async.commit_group;" ::: "memory");
}
template<int N> __device__ __forceinline__ void cp_wait() {
    asm volatile("cp.async.wait_group %0;" :: "n"(N) : "memory");
}
__device__ __forceinline__ void team_bar(int team) {
    asm volatile("bar.sync %0, 128;" :: "r"(1 + team) : "memory");
}
__device__ __forceinline__ float sigf(float x) {
    float e = __expf(-x);
    return __fdividef(1.0f, 1.0f + e);
}
__device__ __forceinline__ float tanh_acc(float x) {
    float ax = fabsf(x);
    float e = __expf(-2.0f * ax);
    float t = __fdividef(1.0f - e, 1.0f + e);
    return copysignf(t, x);
}

// ---------------- Phase 1: input GEMM (+ flag zeroing) ----------------
// grid (8, 1024, 2), 256 threads, dyn smem 133120 B
__global__ void __launch_bounds__(256, 1)
zx_gemm_kernel(const float* __restrict__ xin,
               const float* __restrict__ Wf, const float* __restrict__ bf,
               const float* __restrict__ Wb, const float* __restrict__ bb)
{
    extern __shared__ float zsm[];
    float* Asm = zsm;               // [k][col], pitch 132
    float* Bsm = zsm + 128 * 132;   // [k][n], pitch 128

    const int dir = blockIdx.z;
    const float* W    = dir ? Wb : Wf;
    const float* bias = dir ? bb : bf;
    const int ct = blockIdx.x;
    const int nt = blockIdx.y;
    const int tid = threadIdx.x;

    if (blockIdx.x == 0 && blockIdx.y == 0 && blockIdx.z == 0 && tid < 128)
        ((int*)g_flags)[tid] = 0;

    {
        int c  = tid >> 1;
        int kh = (tid & 1) * 64;
        int colg = ct * 128 + c;
        int g = colg >> 8, h = colg & 255;
        const float* srcA = W + g * 98304 + h * 384 + kh;
        #pragma unroll
        for (int i = 0; i < 64; i += 4) {
            float4 v = *(const float4*)(srcA + i);
            Asm[(kh + i + 0) * 132 + c] = v.x;
            Asm[(kh + i + 1) * 132 + c] = v.y;
            Asm[(kh + i + 2) * 132 + c] = v.z;
            Asm[(kh + i + 3) * 132 + c] = v.w;
        }
    }
    {
        int r  = tid >> 1;
        int nh = (tid & 1) * 64;
        const float* srcB = xin + (size_t)r * NTB + (size_t)nt * 128 + nh;
        #pragma unroll
        for (int i = 0; i < 64; i += 4)
            *(float4*)&Bsm[r * 128 + nh + i] = *(const float4*)(srcB + i);
    }
    __syncthreads();

    const int tn = tid & 15;
    const int tc = tid >> 4;
    const int colt = ct * 128 + tc * 8;

    ull acc[8][4];
    #pragma unroll
    for (int c = 0; c < 8; ++c) {
        ull bd = dup2(bias[colt + c]);
        acc[c][0] = bd; acc[c][1] = bd; acc[c][2] = bd; acc[c][3] = bd;
    }

    #pragma unroll 4
    for (int k = 0; k < 128; ++k) {
        const float* arow = &Asm[k * 132 + tc * 8];
        float4 a0 = *(const float4*)arow;
        float4 a1 = *(const float4*)(arow + 4);
        const longlong2* brow = (const longlong2*)&Bsm[k * 128 + tn * 8];
        longlong2 bA = brow[0], bB = brow[1];
        ull bp0 = (ull)bA.x, bp1 = (ull)bA.y, bp2 = (ull)bB.x, bp3 = (ull)bB.y;
#define ROWF(c, av) { ull ad = dup2(av); \
        fma2(acc[c][0], ad, bp0); fma2(acc[c][1], ad, bp1); \
        fma2(acc[c][2], ad, bp2); fma2(acc[c][3], ad, bp3); }
        ROWF(0, a0.x) ROWF(1, a0.y) ROWF(2, a0.z) ROWF(3, a0.w)
        ROWF(4, a1.x) ROWF(5, a1.y) ROWF(6, a1.z) ROWF(7, a1.w)
#undef ROWF
    }

    float* zd = g_zx + (size_t)dir * ZX_DIR;
    #pragma unroll
    for (int c = 0; c < 8; ++c) {
        size_t base = (size_t)(colt + c) * NTB + (size_t)nt * 128 + (size_t)tn * 8;
        longlong2 v0, v1;
        v0.x = (long long)acc[c][0]; v0.y = (long long)acc[c][1];
        v1.x = (long long)acc[c][2]; v1.y = (long long)acc[c][3];
        *(longlong2*)(zd + base)     = v0;
        *(longlong2*)(zd + base + 4) = v1;
    }
}

// ---------------- Phase 2: persistent recurrence ----------------
// smem: wfiU[(k*8+u)*2 + {f,i}] (32KB), wcoU same for {c,o} (32KB), hsm [k*16+q] (64KB)
__device__ __forceinline__ void kblock(int K0, int K1,
                                       const longlong2* hsmLL, const ull* wfiU, const ull* wcoU,
                                       int u, int q16, ull acc[4][2])
{
    #pragma unroll 8
    for (int k = K0; k < K1; ++k) {
        longlong2 hv  = hsmLL[k * 16 + q16];                       // (h_b0,h_b1),(h_b2,h_b3)
        longlong2 wfi = *(const longlong2*)&wfiU[(k * 8 + u) * 2]; // (wf,wf),(wi,wi)
        longlong2 wco = *(const longlong2*)&wcoU[(k * 8 + u) * 2]; // (wc,wc),(wo,wo)
        fma2(acc[0][0], (ull)hv.x, (ull)wfi.x); fma2(acc[0][1], (ull)hv.y, (ull)wfi.x);
        fma2(acc[1][0], (ull)hv.x, (ull)wfi.y); fma2(acc[1][1], (ull)hv.y, (ull)wfi.y);
        fma2(acc[2][0], (ull)hv.x, (ull)wco.x); fma2(acc[2][1], (ull)hv.y, (ull)wco.x);
        fma2(acc[3][0], (ull)hv.x, (ull)wco.y); fma2(acc[3][1], (ull)hv.y, (ull)wco.y);
    }
}

// grid 128, 256 threads, dyn smem 131072 B
__global__ void __launch_bounds__(256, 1)
lstm_seq_kernel(const float* __restrict__ Wf, const float* __restrict__ Wb,
                float* __restrict__ out)
{
    extern __shared__ float sm[];
    ull*       wfiU  = (ull*)sm;             // 4096 ull
    ull*       wcoU  = (ull*)sm + 4096;      // 4096 ull
    float4*    hsm4  = (float4*)(sm + 16384);
    longlong2* hsmLL = (longlong2*)hsm4;
    ull*       redsm = (ull*)hsm4;           // reduction scratch (reuses h area)

    const int tid  = threadIdx.x;
    const int lane = tid & 31;
    const int warp = tid >> 5;
    const int team = warp >> 2;               // 0: k<128, 1: k>=128
    const int w4   = warp & 3;
    const int u    = lane & 7;                // local unit
    const int q16  = w4 * 4 + (lane >> 3);    // batch quad 0..15

    const int blk  = blockIdx.x;
    const int dirq = blk >> 6;
    const int sub  = blk & 63;
    const int bh   = sub & 1;
    const int ug   = sub >> 1;
    const int uglob = ug * 8 + u;
    const int b0    = bh * 64 + q16 * 4;      // first of this lane's 4 batches

    const float* W = dirq ? Wb : Wf;
    float* hbuf0 = &g_h[dirq][0][0];
    float* hbuf1 = &g_h[dirq][1][0];
    int*   flags = g_flags[dirq];

    // fill duplicated weights: per (k,u): (wf,wf),(wi,wi) and (wc,wc),(wo,wo)
    for (int i = tid; i < 4096; i += 256) {
        int g2 = i & 1, ui = (i >> 1) & 7, k = i >> 4;
        const float* base = W + (ug * 8 + ui) * 384 + 128 + k;
        wfiU[i] = dup2(base[(g2 ? 1 : 0) * 98304]);      // f (g=0), i (g=1)
        wcoU[i] = dup2(base[(g2 ? 3 : 2) * 98304]);      // c (g=2), o (g=3)
    }
    __syncthreads();

    // zx pointers (epilogue threads only)
    const long long zstep = dirq ? -128LL : 128LL;
    const float* zp0; const float* zp1; const float* zp2; const float* zp3;
    {
        const float* zxd = g_zx + (size_t)dirq * ZX_DIR;
        const size_t nb0 = (size_t)(dirq ? (S_LEN - 1) : 0) * 128 + b0;
        zp0 = zxd + (size_t)(0 * 256 + uglob) * NTB + nb0;
        zp1 = zxd + (size_t)(1 * 256 + uglob) * NTB + nb0;
        zp2 = zxd + (size_t)(2 * 256 + uglob) * NTB + nb0;
        zp3 = zxd + (size_t)(3 * 256 + uglob) * NTB + nb0;
    }

    float cst[4] = {0.f, 0.f, 0.f, 0.f};
    float hn[4]  = {0.f, 0.f, 0.f, 0.f};
    const int kbase = team * 128;
    const int tt = tid & 127;

    for (int s = 0; s < S_LEN; ++s) {
        const int t = dirq ? (S_LEN - 1 - s) : s;

        float4 zv0, zv1, zv2, zv3;
        if (tid < 128) {
            zv0 = *(const float4*)zp0; zp0 += zstep;
            zv1 = *(const float4*)zp1; zp1 += zstep;
            zv2 = *(const float4*)zp2; zp2 += zstep;
            zv3 = *(const float4*)zp3; zp3 += zstep;
        }

        ull acc[4][2] = {{0,0},{0,0},{0,0},{0,0}};

        if (s > 0) {
            if (tid < 32) {
                const int* fp = &flags[tid * 2 + bh];
                int v;
                do { asm volatile("ld.acquire.gpu.b32 %0, [%1];" : "=r"(v) : "l"(fp)); }
                while (v < s);
            }
            __syncthreads();

            // stage this team's k-half of h (64 k x 16 quads per chunk)
            const float* hsrc = (s & 1) ? hbuf0 : hbuf1;
            #pragma unroll
            for (int ch = 0; ch < 2; ++ch) {
                int k0 = kbase + ch * 64;
                #pragma unroll
                for (int i = 0; i < 8; ++i) {
                    int o = tt + i * 128;                  // 0..1023
                    int k = k0 + (o >> 4), q = o & 15;
                    cp_async16(&hsm4[k * 16 + q], hsrc + (size_t)k * 128 + bh * 64 + q * 4);
                }
                cp_commit();
            }
            cp_wait<1>(); team_bar(team);
            kblock(kbase, kbase + 64, hsmLL, wfiU, wcoU, u, q16, acc);
            cp_wait<0>(); team_bar(team);
            kblock(kbase + 64, kbase + 128, hsmLL, wfiU, wcoU, u, q16, acc);
        }

        __syncthreads();                       // all kblocks done; h area reusable
        if (team == 1) {
            int c0 = tid - 128;
            #pragma unroll
            for (int g = 0; g < 4; ++g) {
                redsm[(g * 2 + 0) * 128 + c0] = acc[g][0];
                redsm[(g * 2 + 1) * 128 + c0] = acc[g][1];
            }
        }
        __syncthreads();

        if (tid < 128) {
            #pragma unroll
            for (int g = 0; g < 4; ++g) {
                float lo, hi, plo, phi;
                unpack2(redsm[(g * 2 + 0) * 128 + tid], plo, phi);
                unpack2(acc[g][0], lo, hi);
                acc[g][0] = 0;  // reuse as z values below
                float z0 = lo + plo, z1 = hi + phi;
                unpack2(redsm[(g * 2 + 1) * 128 + tid], plo, phi);
                unpack2(acc[g][1], lo, hi);
                float z2 = lo + plo, z3 = hi + phi;
                // stash into a float4 via acc slots (use local array instead)
                ((float*)&acc[g][0])[0] = z0; ((float*)&acc[g][0])[1] = z1;
                ((float*)&acc[g][1])[0] = z2; ((float*)&acc[g][1])[1] = z3;
            }
            float* zF = (float*)&acc[0][0];
            float* zI = (float*)&acc[1][0];
            float* zC = (float*)&acc[2][0];
            float* zO = (float*)&acc[3][0];
            float zxF[4] = {zv0.x, zv0.y, zv0.z, zv0.w};
            float zxI[4] = {zv1.x, zv1.y, zv1.z, zv1.w};
            float zxC[4] = {zv2.x, zv2.y, zv2.z, zv2.w};
            float zxO[4] = {zv3.x, zv3.y, zv3.z, zv3.w};
            #pragma unroll
            for (int bb = 0; bb < 4; ++bb) {
                float fg = sigf(zF[bb] + zxF[bb]);
                float ig = sigf(zI[bb] + zxI[bb]);
                float cg = tanh_acc(zC[bb] + zxC[bb]);
                float og = sigf(zO[bb] + zxO[bb]);
                float cn = fg * cst[bb] + ig * cg;
                cst[bb] = cn;
                hn[bb] = og * tanh_acc(cn);
            }

            float* hwr = (s & 1) ? hbuf1 : hbuf0;
            *(float4*)(hwr + (size_t)uglob * 128 + b0) = make_float4(hn[0], hn[1], hn[2], hn[3]);

            const size_t cix = (size_t)t * 512 + dirq * 256 + uglob;
            #pragma unroll
            for (int bb = 0; bb < 4; ++bb)
                out[(size_t)(b0 + bb) * 524288 + cix] = hn[bb];
        }

        __syncthreads();
        if (tid == 0) {
            int* fp = &flags[sub];
            int v = s + 1;
            asm volatile("st.release.gpu.b32 [%0], %1;" :: "l"(fp), "r"(v) : "memory");
        }
    }

    if (tid < 128) {
        const size_t fin = 67108864ull;
        #pragma unroll
        for (int bb = 0; bb < 4; ++bb) {
            size_t hoff = fin + (size_t)dirq * 32768 + (size_t)(b0 + bb) * 256 + uglob;
            out[hoff]         = hn[bb];
            out[hoff + 65536] = cst[bb];
        }
    }
}

extern "C" void kernel_launch(void* const* d_in, const int* in_sizes, int n_in,
                              void* d_out, int out_size) {
    const float* x  = (const float*)d_in[0];
    const float* Wf = (const float*)d_in[1];
    const float* bf = (const float*)d_in[2];
    const float* Wb = (const float*)d_in[3];
    const float* bb = (const float*)d_in[4];
    float* out = (float*)d_out;

    cudaFuncSetAttribute(zx_gemm_kernel, cudaFuncAttributeMaxDynamicSharedMemorySize, 133120);
    cudaFuncSetAttribute(lstm_seq_kernel, cudaFuncAttributeMaxDynamicSharedMemorySize, 131072);

    dim3 g1(8, 1024, 2);
    zx_gemm_kernel<<<g1, 256, 133120>>>(x, Wf, bf, Wb, bb);
    lstm_seq_kernel<<<128, 256, 131072>>>(Wf, Wb, out);
}